// round 15
// baseline (speedup 1.0000x reference)
#include <cuda_runtime.h>
#include <math.h>

#define B_IMG 8
#define N_PROP 1000
#define C_CLS 91
#define CM1 90
#define NCAND 90000
#define K_TOP 2048
#define DET 36
#define D_FEAT 1024
#define SELMAX 512
#define TARGET 128
#define CHUNK 128
#define NBIN 320
#define BLKS_PER_IMG 63          // 63 blocks x 16 proposals = 1008 >= 1000
#define BBOX_CLIP 4.135166556742356f

typedef unsigned long long u64;
typedef unsigned int u32;

// ---------------- scratch (static device globals; zero-init at load) ---------
__device__ u64    g_list[B_IMG][NCAND];
__device__ float4 g_box[B_IMG][NCAND];   // decoded boxes, indexed by flat
__device__ int    g_M[B_IMG];            // reset by finisher
__device__ int    g_hist[B_IMG][NBIN];   // reset by finisher
__device__ int    g_done[B_IMG];         // reset by finisher

// ---------------- helpers ----------------------------------------------------
__device__ __forceinline__ float4 decode_clip(const float* __restrict__ reg,
                                              const float* __restrict__ props,
                                              int b, u32 flat,
                                              float wImg, float hImg) {
    int n = (int)(flat / CM1);
    int c = (int)(flat % CM1) + 1;
    const float* p = props + ((size_t)b * N_PROP + n) * 4;
    float p0 = p[0], p1 = p[1], p2 = p[2], p3 = p[3];
    float wp = __fsub_rn(p2, p0);
    float hp = __fsub_rn(p3, p1);
    float cx = __fadd_rn(p0, __fmul_rn(0.5f, wp));
    float cy = __fadd_rn(p1, __fmul_rn(0.5f, hp));
    const float* r = reg + ((size_t)b * N_PROP + n) * (C_CLS * 4) + c * 4;
    float dx = __fdiv_rn(r[0], 10.0f);
    float dy = __fdiv_rn(r[1], 10.0f);
    float dw = fminf(__fdiv_rn(r[2], 5.0f), BBOX_CLIP);
    float dh = fminf(__fdiv_rn(r[3], 5.0f), BBOX_CLIP);
    float pcx = __fadd_rn(__fmul_rn(dx, wp), cx);
    float pcy = __fadd_rn(__fmul_rn(dy, hp), cy);
    float pw  = __fmul_rn(expf(dw), wp);
    float ph  = __fmul_rn(expf(dh), hp);
    float x1 = __fsub_rn(pcx, __fmul_rn(0.5f, pw));
    float y1 = __fsub_rn(pcy, __fmul_rn(0.5f, ph));
    float x2 = __fadd_rn(pcx, __fmul_rn(0.5f, pw));
    float y2 = __fadd_rn(pcy, __fmul_rn(0.5f, ph));
    x1 = fminf(fmaxf(x1, 0.0f), wImg);
    y1 = fminf(fmaxf(y1, 0.0f), hImg);
    x2 = fminf(fmaxf(x2, 0.0f), wImg);
    y2 = fminf(fmaxf(y2, 0.0f), hImg);
    return make_float4(x1, y1, x2, y2);
}

__device__ __forceinline__ bool iou_gt_half(float4 a, float areaA, float4 c) {
    float ltx = fmaxf(a.x, c.x), lty = fmaxf(a.y, c.y);
    float rbx = fminf(a.z, c.z), rby = fminf(a.w, c.w);
    float w = fmaxf(__fsub_rn(rbx, ltx), 0.0f);
    float h = fmaxf(__fsub_rn(rby, lty), 0.0f);
    float inter = __fmul_rn(w, h);
    if (inter <= 0.0f) return false;
    float areaC = __fmul_rn(__fsub_rn(c.z, c.x), __fsub_rn(c.w, c.y));
    float uni = __fsub_rn(__fadd_rn(areaA, areaC), inter);
    return __fdiv_rn(inter, uni) > 0.5f;
}

__device__ __forceinline__ int score_bin(u32 sb) {
    int bin = (int)(sb >> 16) - 15948;
    return bin < 0 ? 0 : (bin > NBIN - 1 ? NBIN - 1 : bin);
}

// ---------------- 4-key/thread register bitonic primitives -------------------
__device__ __forceinline__ u64 cex(u64 v, u64 p, bool takeMax) {
    return takeMax ? (v > p ? v : p) : (v < p ? v : p);
}
__device__ __forceinline__ void cswap(u64& a, u64& b, bool desc) {
    u64 hi = a > b ? a : b, lo = a > b ? b : a;
    a = desc ? hi : lo;
    b = desc ? lo : hi;
}
__device__ __forceinline__ void smem_step(u64 v[4], u64* buf, const int idx[4],
                                          int j, int k, bool active) {
    if (active) {
        #pragma unroll
        for (int r = 0; r < 4; ++r) buf[idx[r]] = v[r];
    }
    __syncthreads();
    if (active) {
        #pragma unroll
        for (int r = 0; r < 4; ++r) {
            u64 p = buf[idx[r] ^ j];
            v[r] = cex(v[r], p, ((idx[r] & j) == 0) == ((idx[r] & k) == 0));
        }
    }
    __syncthreads();
}
__device__ __forceinline__ void reg_tail(u64 v[4], const int idx[4], int lane,
                                         int k, int jstart) {
    if (jstart >= 64) {
        bool d = (k == 0) || ((idx[0] & k) == 0);
        cswap(v[0], v[2], d);
        cswap(v[1], v[3], d);
    }
    if (jstart >= 32) {
        bool d01 = (k == 0) || ((idx[0] & k) == 0);
        bool d23 = (k == 0) || ((idx[2] & k) == 0);
        cswap(v[0], v[1], d01);
        cswap(v[2], v[3], d23);
    }
    int j0 = jstart < 16 ? jstart : 16;
    for (int j = j0; j >= 1; j >>= 1) {
        #pragma unroll
        for (int r = 0; r < 4; ++r) {
            u64 p = __shfl_xor_sync(0xffffffffu, v[r], j);
            bool desc = (k == 0) || ((idx[r] & k) == 0);
            v[r] = cex(v[r], p, ((lane & j) == 0) == desc);
        }
    }
}
__device__ void sort_n(u64 v[4], u64* buf, const int idx[4], int lane, int n) {
    for (int k = 2; k <= n; k <<= 1) {
        bool active = (idx[0] < n);
        for (int j = k >> 1; j >= 128; j >>= 1)
            smem_step(v, buf, idx, j, k, active);
        if (active) reg_tail(v, idx, lane, k, k >> 1);
    }
}

// ---------------- tail shared state -------------------------------------------
struct TailShared {
    u64    keys[K_TOP];         // 16KB
    u64    selbuf[SELMAX];      // 4KB
    float4 cbox[CHUNK];
    u32    mask32[CHUNK][4];
    float4 kbox[DET];
    float  karea[DET];
    int    pprop[DET];
    int    skept[DET];
    int    s_kc, s_T, s_cnt, s_cntAb, s_pos;
    u64    aw[2];
    int    finisher;
};

// Chunked exact greedy NMS over sorted keys[0..limit). 512 threads.
__device__ int nms_chunks(const u64* keys, int limit, int b,
                          TailShared* S, int tid) {
    int kc = 0;
    for (int c0 = 0; c0 < limit && kc < DET; c0 += CHUNK) {
        int csz = min(limit - c0, CHUNK);
        if (tid < csz) {
            u32 flat = ~(u32)(keys[c0 + tid] & 0xffffffffull);
            S->cbox[tid] = g_box[b][flat];          // precomputed box, 1 LDG.128
        }
        if (tid < 2) {
            int lo = tid * 64, nb = csz - lo;
            S->aw[tid] = (nb <= 0) ? 0ull : (nb >= 64 ? ~0ull : ((1ull << nb) - 1ull));
        }
        __syncthreads();
        if (c0 > 0) {
            if (tid < csz) {
                float4 cb = S->cbox[tid];
                bool al = true;
                for (int t = 0; t < kc; ++t)
                    if (iou_gt_half(S->kbox[t], S->karea[t], cb)) { al = false; break; }
                if (!al) atomicAnd(&S->aw[tid >> 6], ~(1ull << (tid & 63)));
            }
            __syncthreads();
        }
        {
            int q = tid >> 2, w = tid & 3;
            u32 m = 0;
            if (q < csz) {
                float4 a = S->cbox[q];
                float areaA = __fmul_rn(__fsub_rn(a.z, a.x), __fsub_rn(a.w, a.y));
                int jb = w * 32;
                int je = csz - jb; je = je > 32 ? 32 : je;
                for (int jj = (q + 1 > jb ? q + 1 - jb : 0); jj < je; ++jj)
                    if (iou_gt_half(a, areaA, S->cbox[jb + jj])) m |= (1u << jj);
            }
            S->mask32[q][w] = m;
        }
        __syncthreads();
        if (tid == 0) {
            u64 a0 = S->aw[0], a1 = S->aw[1];
            int k2 = kc;
            while (k2 < DET) {
                int q;
                if (a0) q = __ffsll((long long)a0) - 1;
                else if (a1) q = 64 + __ffsll((long long)a1) - 1;
                else break;
                S->skept[k2++] = c0 + q;
                u64 m0 = (u64)S->mask32[q][0] | ((u64)S->mask32[q][1] << 32);
                u64 m1 = (u64)S->mask32[q][2] | ((u64)S->mask32[q][3] << 32);
                if (q < 64) m0 |= (1ull << q); else m1 |= (1ull << (q - 64));
                a0 &= ~m0; a1 &= ~m1;
            }
            S->s_kc = k2;
        }
        __syncthreads();
        int knew = S->s_kc;
        int t = kc + tid;
        if (t < knew) {
            int q = S->skept[t] - c0;
            float4 a = S->cbox[q];
            S->kbox[t] = a;
            S->karea[t] = __fmul_rn(__fsub_rn(a.z, a.x), __fsub_rn(a.w, a.y));
            u32 flat = ~(u32)(keys[S->skept[t]] & 0xffffffffull);
            S->pprop[t] = (int)(flat / CM1);
        }
        __syncthreads();
        kc = knew;
    }
    return kc;
}

// ---------------- fused kernel: score + (finisher) tail ----------------------
// grid = B_IMG * BLKS_PER_IMG blocks, 512 threads (16 warps = 16 proposals)
__global__ __launch_bounds__(512, 3)
void fused_kernel(const float* __restrict__ logits,
                  const float* __restrict__ reg,
                  const float* __restrict__ props,
                  const int*   __restrict__ img_hw,
                  const float* __restrict__ feats,
                  float* __restrict__ out) {
    __shared__ TailShared S;

    int b = blockIdx.x / BLKS_PER_IMG;
    int blk = blockIdx.x % BLKS_PER_IMG;
    int tid = threadIdx.x;
    int wid = tid >> 5, lane = tid & 31;
    int n = blk * 16 + wid;

    float hImg = (float)img_hw[b * 2 + 0];
    float wImg = (float)img_hw[b * 2 + 1];

    // ================= score phase (one proposal per warp) =================
    if (n < N_PROP) {
        const float* lrow = logits + ((size_t)b * N_PROP + n) * C_CLS;
        float l0 = lrow[lane];
        float l1 = (lane + 32 < C_CLS) ? lrow[lane + 32] : -INFINITY;
        float l2 = (lane + 64 < C_CLS) ? lrow[lane + 64] : -INFINITY;

        float m = fmaxf(fmaxf(l0, l2), l1);
        #pragma unroll
        for (int s = 16; s > 0; s >>= 1)
            m = fmaxf(m, __shfl_xor_sync(0xffffffffu, m, s));
        m = __shfl_sync(0xffffffffu, m, 0);

        float e0 = expf(__fsub_rn(l0, m));
        float e1 = expf(__fsub_rn(l1, m));
        float e2 = expf(__fsub_rn(l2, m));

        float v = __fadd_rn(__fadd_rn(e0, e2), e1);
        #pragma unroll
        for (int s = 16; s > 0; s >>= 1)
            v = __fadd_rn(v, __shfl_xor_sync(0xffffffffu, v, s));
        float ssum = __shfl_sync(0xffffffffu, v, 0);

        float ecls[3] = {e0, e1, e2};
        #pragma unroll
        for (int k = 0; k < 3; ++k) {
            int c = lane + 32 * k;
            if (c >= 1 && c < C_CLS) {
                float score = __fdiv_rn(ecls[k], ssum);
                if (score > 0.2f) {
                    u32 flat = (u32)(n * CM1 + (c - 1));
                    float4 box = decode_clip(reg, props, b, flat, wImg, hImg);
                    if (__fsub_rn(box.z, box.x) >= 0.01f &&
                        __fsub_rn(box.w, box.y) >= 0.01f) {
                        u32 sb = __float_as_uint(score);
                        int pos = atomicAdd(&g_M[b], 1);
                        u64 key = ((u64)sb << 32) | (u64)(u32)(~flat);
                        g_list[b][pos] = key;
                        g_box[b][flat] = box;             // bit-identical decode
                        atomicAdd(&g_hist[b][score_bin(sb)], 1);
                    }
                }
            }
        }
    }
    __syncthreads();

    // ================= last-block-done handoff =================
    if (tid == 0) {
        __threadfence();
        int prev = atomicAdd(&g_done[b], 1);
        S.finisher = (prev == BLKS_PER_IMG - 1) ? 1 : 0;
    }
    __syncthreads();
    if (!S.finisher) return;
    __threadfence();          // acquire: all other blocks' writes visible

    // ================= tail phase (this block only) =================
    int M = g_M[b];
    if (tid == 0) { S.s_pos = 0; S.s_kc = 0; }

    // threshold: warp 0, 10 bins/lane suffix scan reading g_hist directly
    if (tid < 32) {
        int lb[10]; int lsum = 0;
        #pragma unroll
        for (int r = 0; r < 10; ++r) { lb[r] = g_hist[b][lane * 10 + r]; lsum += lb[r]; }
        int suf = lsum;
        #pragma unroll
        for (int s = 1; s < 32; s <<= 1) {
            int o = __shfl_down_sync(0xffffffffu, suf, s);
            if (lane + s < 32) suf += o;
        }
        int sufN = __shfl_down_sync(0xffffffffu, suf, 1);
        if (lane == 31) sufN = 0;
        u32 ball = __ballot_sync(0xffffffffu, suf >= TARGET);
        if (ball == 0) {
            if (lane == 0) { S.s_T = 0; S.s_cnt = suf; S.s_cntAb = 0; }
        } else {
            int L = 31 - __clz(ball);
            if (lane == L) {
                int cum = sufN, T = 0, cnt = suf, cA = sufN;
                for (int r = 9; r >= 0; --r) {
                    cum += lb[r];
                    if (cum >= TARGET) { T = L * 10 + r; cnt = cum; cA = cum - lb[r]; break; }
                }
                S.s_T = T; S.s_cnt = cnt; S.s_cntAb = cA;
            }
        }
    }
    __syncthreads();

    bool useGT = S.s_cnt > SELMAX;
    int thr = S.s_T;
    int cnt2 = useGT ? S.s_cntAb : S.s_cnt;

    // compact selected keys
    for (int s = tid; s < M; s += 512) {
        u64 key = g_list[b][s];
        int bin = score_bin((u32)(key >> 32));
        bool selb = useGT ? (bin > thr) : (bin >= thr);
        if (selb) { int p = atomicAdd(&S.s_pos, 1); S.selbuf[p] = key; }
    }
    __syncthreads();

    // sort <=512 selected keys
    int n2 = 128;
    while (n2 < cnt2) n2 <<= 1;
    int base = ((tid >> 5) << 7) + lane;
    int idx[4] = {base, base + 32, base + 64, base + 96};
    {
        u64 v[4];
        #pragma unroll
        for (int r = 0; r < 4; ++r)
            v[r] = (idx[r] < cnt2) ? S.selbuf[idx[r]] : 0ull;
        sort_n(v, S.keys, idx, lane, n2);
        #pragma unroll
        for (int r = 0; r < 4; ++r) if (idx[r] < n2) S.keys[idx[r]] = v[r];
    }
    __syncthreads();

    int K = min(M, K_TOP);

    // chunked exact greedy NMS over sorted selected keys
    int kc = nms_chunks(S.keys, cnt2, b, &S, tid);

    // rare exact full path
    if (kc < DET && K > cnt2) {
        int loaded = K;
        int n3 = 128;
        while (n3 < loaded) n3 <<= 1;
        u64 v[4];
        #pragma unroll
        for (int r = 0; r < 4; ++r)
            v[r] = (idx[r] < loaded) ? g_list[b][idx[r]] : 0ull;
        __syncthreads();
        sort_n(v, S.keys, idx, lane, n3);

        int consumed = loaded;
        while (consumed < M) {
            int take = min(M - consumed, K_TOP);
            u64 u[4];
            #pragma unroll
            for (int r = 0; r < 4; ++r)
                u[r] = (idx[r] < take) ? g_list[b][consumed + idx[r]] : 0ull;
            consumed += take;
            sort_n(u, S.keys, idx, lane, K_TOP);
            #pragma unroll
            for (int r = 0; r < 4; ++r) S.keys[idx[r]] = u[r];
            __syncthreads();
            #pragma unroll
            for (int r = 0; r < 4; ++r) {
                u64 p = S.keys[2047 ^ idx[r]];
                v[r] = v[r] > p ? v[r] : p;
            }
            __syncthreads();
            for (int j = 1024; j >= 128; j >>= 1)
                smem_step(v, S.keys, idx, j, 0, true);
            reg_tail(v, idx, lane, 0, 64);
            n3 = K_TOP;
        }
        #pragma unroll
        for (int r = 0; r < 4; ++r) if (idx[r] < n3) S.keys[idx[r]] = v[r];
        if (tid == 0) S.s_kc = 0;
        __syncthreads();

        kc = nms_chunks(S.keys, K, b, &S, tid);
    }

    // feature gather (36 rows x 256 float4)
    for (int id = tid; id < DET * (D_FEAT / 4); id += 512) {
        int t = id >> 8, q = id & 255;
        float4* dst = (float4*)(out + ((size_t)b * DET + t) * D_FEAT);
        if (t < kc) {
            const float4* src =
                (const float4*)(feats + ((size_t)b * N_PROP + S.pprop[t]) * D_FEAT);
            dst[q] = src[q];
        } else {
            dst[q] = make_float4(0.f, 0.f, 0.f, 0.f);
        }
    }

    // resets for next graph replay
    if (tid < NBIN) g_hist[b][tid] = 0;
    if (tid == 0) { g_M[b] = 0; g_done[b] = 0; }
}

// ---------------- launch ------------------------------------------------------
extern "C" void kernel_launch(void* const* d_in, const int* in_sizes, int n_in,
                              void* d_out, int out_size) {
    const float* logits = (const float*)d_in[0];
    const float* reg    = (const float*)d_in[1];
    const float* props  = (const float*)d_in[2];
    const float* feats  = (const float*)d_in[3];
    const int*   imghw  = (const int*)d_in[4];
    float* out = (float*)d_out;

    fused_kernel<<<B_IMG * BLKS_PER_IMG, 512>>>(logits, reg, props, imghw,
                                                feats, out);
}

// round 16
// speedup vs baseline: 1.0604x; 1.0604x over previous
#include <cuda_runtime.h>
#include <math.h>

#define B_IMG 8
#define N_PROP 1000
#define C_CLS 91
#define CM1 90
#define NCAND 90000
#define K_TOP 2048
#define DET 36
#define D_FEAT 1024
#define SELMAX 512
#define TARGET 128
#define CHUNK 128
#define NBIN 320
#define BBOX_CLIP 4.135166556742356f

typedef unsigned long long u64;
typedef unsigned int u32;

// ---------------- scratch (static device globals; zero-init at load) ---------
__device__ u64    g_list[B_IMG][NCAND];
__device__ float4 g_box[B_IMG][NCAND];   // decoded boxes, indexed by flat
__device__ int    g_M[B_IMG];            // reset by tail_kernel
__device__ int    g_hist[B_IMG][NBIN];   // reset by tail_kernel

// ---------------- helpers ----------------------------------------------------
__device__ __forceinline__ float4 decode_clip(const float* __restrict__ reg,
                                              const float* __restrict__ props,
                                              int b, u32 flat,
                                              float wImg, float hImg) {
    int n = (int)(flat / CM1);
    int c = (int)(flat % CM1) + 1;
    const float* p = props + ((size_t)b * N_PROP + n) * 4;
    float p0 = p[0], p1 = p[1], p2 = p[2], p3 = p[3];
    float wp = __fsub_rn(p2, p0);
    float hp = __fsub_rn(p3, p1);
    float cx = __fadd_rn(p0, __fmul_rn(0.5f, wp));
    float cy = __fadd_rn(p1, __fmul_rn(0.5f, hp));
    const float* r = reg + ((size_t)b * N_PROP + n) * (C_CLS * 4) + c * 4;
    float dx = __fdiv_rn(r[0], 10.0f);
    float dy = __fdiv_rn(r[1], 10.0f);
    float dw = fminf(__fdiv_rn(r[2], 5.0f), BBOX_CLIP);
    float dh = fminf(__fdiv_rn(r[3], 5.0f), BBOX_CLIP);
    float pcx = __fadd_rn(__fmul_rn(dx, wp), cx);
    float pcy = __fadd_rn(__fmul_rn(dy, hp), cy);
    float pw  = __fmul_rn(expf(dw), wp);
    float ph  = __fmul_rn(expf(dh), hp);
    float x1 = __fsub_rn(pcx, __fmul_rn(0.5f, pw));
    float y1 = __fsub_rn(pcy, __fmul_rn(0.5f, ph));
    float x2 = __fadd_rn(pcx, __fmul_rn(0.5f, pw));
    float y2 = __fadd_rn(pcy, __fmul_rn(0.5f, ph));
    x1 = fminf(fmaxf(x1, 0.0f), wImg);
    y1 = fminf(fmaxf(y1, 0.0f), hImg);
    x2 = fminf(fmaxf(x2, 0.0f), wImg);
    y2 = fminf(fmaxf(y2, 0.0f), hImg);
    return make_float4(x1, y1, x2, y2);
}

__device__ __forceinline__ bool iou_gt_half(float4 a, float areaA, float4 c) {
    float ltx = fmaxf(a.x, c.x), lty = fmaxf(a.y, c.y);
    float rbx = fminf(a.z, c.z), rby = fminf(a.w, c.w);
    float w = fmaxf(__fsub_rn(rbx, ltx), 0.0f);
    float h = fmaxf(__fsub_rn(rby, lty), 0.0f);
    float inter = __fmul_rn(w, h);
    if (inter <= 0.0f) return false;
    float areaC = __fmul_rn(__fsub_rn(c.z, c.x), __fsub_rn(c.w, c.y));
    float uni = __fsub_rn(__fadd_rn(areaA, areaC), inter);
    return __fdiv_rn(inter, uni) > 0.5f;
}

__device__ __forceinline__ int score_bin(u32 sb) {
    int bin = (int)(sb >> 16) - 15948;
    return bin < 0 ? 0 : (bin > NBIN - 1 ? NBIN - 1 : bin);
}

// ---------------- kernel 1: softmax + filter + compact + hist + box ----------
__global__ __launch_bounds__(256)
void score_kernel(const float* __restrict__ logits,
                  const float* __restrict__ reg,
                  const float* __restrict__ props,
                  const int*   __restrict__ img_hw) {
    int warp = (blockIdx.x * blockDim.x + threadIdx.x) >> 5;
    int lane = threadIdx.x & 31;
    int b = warp / N_PROP;
    int n = warp % N_PROP;

    const float* lrow = logits + (size_t)warp * C_CLS;
    float l0 = lrow[lane];
    float l1 = (lane + 32 < C_CLS) ? lrow[lane + 32] : -INFINITY;
    float l2 = (lane + 64 < C_CLS) ? lrow[lane + 64] : -INFINITY;

    float m = fmaxf(fmaxf(l0, l2), l1);
    #pragma unroll
    for (int s = 16; s > 0; s >>= 1)
        m = fmaxf(m, __shfl_xor_sync(0xffffffffu, m, s));
    m = __shfl_sync(0xffffffffu, m, 0);

    float e0 = expf(__fsub_rn(l0, m));
    float e1 = expf(__fsub_rn(l1, m));
    float e2 = expf(__fsub_rn(l2, m));

    float v = __fadd_rn(__fadd_rn(e0, e2), e1);
    #pragma unroll
    for (int s = 16; s > 0; s >>= 1)
        v = __fadd_rn(v, __shfl_xor_sync(0xffffffffu, v, s));
    float ssum = __shfl_sync(0xffffffffu, v, 0);

    float hImg = (float)img_hw[b * 2 + 0];
    float wImg = (float)img_hw[b * 2 + 1];

    float ecls[3] = {e0, e1, e2};
    #pragma unroll
    for (int k = 0; k < 3; ++k) {
        int c = lane + 32 * k;
        if (c >= 1 && c < C_CLS) {
            float score = __fdiv_rn(ecls[k], ssum);
            if (score > 0.2f) {
                u32 flat = (u32)(n * CM1 + (c - 1));
                float4 box = decode_clip(reg, props, b, flat, wImg, hImg);
                if (__fsub_rn(box.z, box.x) >= 0.01f &&
                    __fsub_rn(box.w, box.y) >= 0.01f) {
                    u32 sb = __float_as_uint(score);
                    int pos = atomicAdd(&g_M[b], 1);
                    u64 key = ((u64)sb << 32) | (u64)(u32)(~flat);
                    g_list[b][pos] = key;
                    g_box[b][flat] = box;          // bit-identical decode
                    atomicAdd(&g_hist[b][score_bin(sb)], 1);
                }
            }
        }
    }
}

// ---------------- 4-key/thread register bitonic primitives -------------------
__device__ __forceinline__ u64 cex(u64 v, u64 p, bool takeMax) {
    return takeMax ? (v > p ? v : p) : (v < p ? v : p);
}
__device__ __forceinline__ void cswap(u64& a, u64& b, bool desc) {
    u64 hi = a > b ? a : b, lo = a > b ? b : a;
    a = desc ? hi : lo;
    b = desc ? lo : hi;
}
__device__ __forceinline__ void smem_step(u64 v[4], u64* buf, const int idx[4],
                                          int j, int k, bool active) {
    if (active) {
        #pragma unroll
        for (int r = 0; r < 4; ++r) buf[idx[r]] = v[r];
    }
    __syncthreads();
    if (active) {
        #pragma unroll
        for (int r = 0; r < 4; ++r) {
            u64 p = buf[idx[r] ^ j];
            v[r] = cex(v[r], p, ((idx[r] & j) == 0) == ((idx[r] & k) == 0));
        }
    }
    __syncthreads();
}
__device__ __forceinline__ void reg_tail(u64 v[4], const int idx[4], int lane,
                                         int k, int jstart) {
    if (jstart >= 64) {
        bool d = (k == 0) || ((idx[0] & k) == 0);
        cswap(v[0], v[2], d);
        cswap(v[1], v[3], d);
    }
    if (jstart >= 32) {
        bool d01 = (k == 0) || ((idx[0] & k) == 0);
        bool d23 = (k == 0) || ((idx[2] & k) == 0);
        cswap(v[0], v[1], d01);
        cswap(v[2], v[3], d23);
    }
    int j0 = jstart < 16 ? jstart : 16;
    for (int j = j0; j >= 1; j >>= 1) {
        #pragma unroll
        for (int r = 0; r < 4; ++r) {
            u64 p = __shfl_xor_sync(0xffffffffu, v[r], j);
            bool desc = (k == 0) || ((idx[r] & k) == 0);
            v[r] = cex(v[r], p, ((lane & j) == 0) == desc);
        }
    }
}
__device__ void sort_n(u64 v[4], u64* buf, const int idx[4], int lane, int n) {
    for (int k = 2; k <= n; k <<= 1) {
        bool active = (idx[0] < n);
        for (int j = k >> 1; j >= 128; j >>= 1)
            smem_step(v, buf, idx, j, k, active);
        if (active) reg_tail(v, idx, lane, k, k >> 1);
    }
}

// ---------------- tail shared state -------------------------------------------
struct TailShared {
    u64    keys[K_TOP];         // 16KB
    u64    selbuf[SELMAX];      // 4KB
    float4 cbox[CHUNK];
    u32    mask32[CHUNK][4];
    float4 kbox[DET];
    float  karea[DET];
    int    pprop[DET];
    int    skept[DET];
    int    s_kc, s_T, s_cnt, s_cntAb, s_pos;
    u64    aw[2];
};

// Chunked exact greedy NMS over sorted keys[0..limit). 512 threads.
__device__ int nms_chunks(const u64* keys, int limit, int b,
                          TailShared* S, int tid) {
    int kc = 0;
    for (int c0 = 0; c0 < limit && kc < DET; c0 += CHUNK) {
        int csz = min(limit - c0, CHUNK);
        if (tid < csz) {
            u32 flat = ~(u32)(keys[c0 + tid] & 0xffffffffull);
            S->cbox[tid] = g_box[b][flat];          // precomputed box
        }
        if (tid < 2) {
            int lo = tid * 64, nb = csz - lo;
            S->aw[tid] = (nb <= 0) ? 0ull : (nb >= 64 ? ~0ull : ((1ull << nb) - 1ull));
        }
        __syncthreads();
        if (c0 > 0) {
            if (tid < csz) {
                float4 cb = S->cbox[tid];
                bool al = true;
                for (int t = 0; t < kc; ++t)
                    if (iou_gt_half(S->kbox[t], S->karea[t], cb)) { al = false; break; }
                if (!al) atomicAnd(&S->aw[tid >> 6], ~(1ull << (tid & 63)));
            }
            __syncthreads();
        }
        {
            int q = tid >> 2, w = tid & 3;
            u32 m = 0;
            if (q < csz) {
                float4 a = S->cbox[q];
                float areaA = __fmul_rn(__fsub_rn(a.z, a.x), __fsub_rn(a.w, a.y));
                int jb = w * 32;
                int je = csz - jb; je = je > 32 ? 32 : je;
                for (int jj = (q + 1 > jb ? q + 1 - jb : 0); jj < je; ++jj)
                    if (iou_gt_half(a, areaA, S->cbox[jb + jj])) m |= (1u << jj);
            }
            S->mask32[q][w] = m;
        }
        __syncthreads();
        if (tid == 0) {
            u64 a0 = S->aw[0], a1 = S->aw[1];
            int k2 = kc;
            while (k2 < DET) {
                int q;
                if (a0) q = __ffsll((long long)a0) - 1;
                else if (a1) q = 64 + __ffsll((long long)a1) - 1;
                else break;
                S->skept[k2++] = c0 + q;
                u64 m0 = (u64)S->mask32[q][0] | ((u64)S->mask32[q][1] << 32);
                u64 m1 = (u64)S->mask32[q][2] | ((u64)S->mask32[q][3] << 32);
                if (q < 64) m0 |= (1ull << q); else m1 |= (1ull << (q - 64));
                a0 &= ~m0; a1 &= ~m1;
            }
            S->s_kc = k2;
        }
        __syncthreads();
        int knew = S->s_kc;
        int t = kc + tid;
        if (t < knew) {
            int q = S->skept[t] - c0;
            float4 a = S->cbox[q];
            S->kbox[t] = a;
            S->karea[t] = __fmul_rn(__fsub_rn(a.z, a.x), __fsub_rn(a.w, a.y));
            u32 flat = ~(u32)(keys[S->skept[t]] & 0xffffffffull);
            S->pprop[t] = (int)(flat / CM1);
        }
        __syncthreads();
        kc = knew;
    }
    return kc;
}

// ---------------- kernel 2: select + sort + chunked NMS + gather -------------
// one block per image, 512 threads
__global__ __launch_bounds__(512)
void tail_kernel(const float* __restrict__ feats,
                 float* __restrict__ out) {
    __shared__ TailShared S;

    int b = blockIdx.x, tid = threadIdx.x, lane = tid & 31;
    int M = g_M[b];

    // ---- speculative key preload (overlaps with threshold's g_hist reads) ----
    u64 pk0 = (tid < M) ? g_list[b][tid] : 0ull;
    u64 pk1 = (tid + 512 < M) ? g_list[b][tid + 512] : 0ull;

    if (tid == 0) { S.s_pos = 0; S.s_kc = 0; }

    // ---- threshold: warp 0, 10 bins/lane suffix scan on g_hist directly ----
    if (tid < 32) {
        int lb[10]; int lsum = 0;
        #pragma unroll
        for (int r = 0; r < 10; ++r) { lb[r] = g_hist[b][lane * 10 + r]; lsum += lb[r]; }
        int suf = lsum;
        #pragma unroll
        for (int s = 1; s < 32; s <<= 1) {
            int o = __shfl_down_sync(0xffffffffu, suf, s);
            if (lane + s < 32) suf += o;
        }
        int sufN = __shfl_down_sync(0xffffffffu, suf, 1);
        if (lane == 31) sufN = 0;
        u32 ball = __ballot_sync(0xffffffffu, suf >= TARGET);
        if (ball == 0) {
            if (lane == 0) { S.s_T = 0; S.s_cnt = suf; S.s_cntAb = 0; }
        } else {
            int L = 31 - __clz(ball);
            if (lane == L) {
                int cum = sufN, T = 0, cnt = suf, cA = sufN;
                for (int r = 9; r >= 0; --r) {
                    cum += lb[r];
                    if (cum >= TARGET) { T = L * 10 + r; cnt = cum; cA = cum - lb[r]; break; }
                }
                S.s_T = T; S.s_cnt = cnt; S.s_cntAb = cA;
            }
        }
    }
    __syncthreads();

    bool useGT = S.s_cnt > SELMAX;
    int thr = S.s_T;
    int cnt2 = useGT ? S.s_cntAb : S.s_cnt;

    // ---- compact selected keys (preloaded pair first, loop for M > 1024) ----
    {
        if (tid < M) {
            int bin = score_bin((u32)(pk0 >> 32));
            bool selb = useGT ? (bin > thr) : (bin >= thr);
            if (selb) { int p = atomicAdd(&S.s_pos, 1); S.selbuf[p] = pk0; }
        }
        if (tid + 512 < M) {
            int bin = score_bin((u32)(pk1 >> 32));
            bool selb = useGT ? (bin > thr) : (bin >= thr);
            if (selb) { int p = atomicAdd(&S.s_pos, 1); S.selbuf[p] = pk1; }
        }
        for (int s = 1024 + tid; s < M; s += 512) {
            u64 key = g_list[b][s];
            int bin = score_bin((u32)(key >> 32));
            bool selb = useGT ? (bin > thr) : (bin >= thr);
            if (selb) { int p = atomicAdd(&S.s_pos, 1); S.selbuf[p] = key; }
        }
    }
    __syncthreads();

    // ---- sort <=512 selected keys ----
    int n2 = 128;
    while (n2 < cnt2) n2 <<= 1;
    int base = ((tid >> 5) << 7) + lane;
    int idx[4] = {base, base + 32, base + 64, base + 96};
    {
        u64 v[4];
        #pragma unroll
        for (int r = 0; r < 4; ++r)
            v[r] = (idx[r] < cnt2) ? S.selbuf[idx[r]] : 0ull;
        sort_n(v, S.keys, idx, lane, n2);
        #pragma unroll
        for (int r = 0; r < 4; ++r) if (idx[r] < n2) S.keys[idx[r]] = v[r];
    }
    __syncthreads();

    int K = min(M, K_TOP);

    // ---- chunked exact greedy NMS over sorted selected keys ----
    int kc = nms_chunks(S.keys, cnt2, b, &S, tid);

    // ---- rare exact full path ----
    if (kc < DET && K > cnt2) {
        int loaded = K;
        int n3 = 128;
        while (n3 < loaded) n3 <<= 1;
        u64 v[4];
        #pragma unroll
        for (int r = 0; r < 4; ++r)
            v[r] = (idx[r] < loaded) ? g_list[b][idx[r]] : 0ull;
        __syncthreads();
        sort_n(v, S.keys, idx, lane, n3);

        int consumed = loaded;
        while (consumed < M) {
            int take = min(M - consumed, K_TOP);
            u64 u[4];
            #pragma unroll
            for (int r = 0; r < 4; ++r)
                u[r] = (idx[r] < take) ? g_list[b][consumed + idx[r]] : 0ull;
            consumed += take;
            sort_n(u, S.keys, idx, lane, K_TOP);
            #pragma unroll
            for (int r = 0; r < 4; ++r) S.keys[idx[r]] = u[r];
            __syncthreads();
            #pragma unroll
            for (int r = 0; r < 4; ++r) {
                u64 p = S.keys[2047 ^ idx[r]];
                v[r] = v[r] > p ? v[r] : p;
            }
            __syncthreads();
            for (int j = 1024; j >= 128; j >>= 1)
                smem_step(v, S.keys, idx, j, 0, true);
            reg_tail(v, idx, lane, 0, 64);
            n3 = K_TOP;
        }
        #pragma unroll
        for (int r = 0; r < 4; ++r) if (idx[r] < n3) S.keys[idx[r]] = v[r];
        if (tid == 0) S.s_kc = 0;
        __syncthreads();

        kc = nms_chunks(S.keys, K, b, &S, tid);
    }

    // ---- feature gather (36 rows x 256 float4) ----
    for (int id = tid; id < DET * (D_FEAT / 4); id += 512) {
        int t = id >> 8, q = id & 255;
        float4* dst = (float4*)(out + ((size_t)b * DET + t) * D_FEAT);
        if (t < kc) {
            const float4* src =
                (const float4*)(feats + ((size_t)b * N_PROP + S.pprop[t]) * D_FEAT);
            dst[q] = src[q];
        } else {
            dst[q] = make_float4(0.f, 0.f, 0.f, 0.f);
        }
    }

    // ---- resets for next graph replay ----
    if (tid < NBIN) g_hist[b][tid] = 0;
    if (tid == 0) g_M[b] = 0;
}

// ---------------- launch ------------------------------------------------------
extern "C" void kernel_launch(void* const* d_in, const int* in_sizes, int n_in,
                              void* d_out, int out_size) {
    const float* logits = (const float*)d_in[0];
    const float* reg    = (const float*)d_in[1];
    const float* props  = (const float*)d_in[2];
    const float* feats  = (const float*)d_in[3];
    const int*   imghw  = (const int*)d_in[4];
    float* out = (float*)d_out;

    score_kernel<<<B_IMG * N_PROP / 8, 256>>>(logits, reg, props, imghw);
    tail_kernel<<<B_IMG, 512>>>(feats, out);
}